// round 2
// baseline (speedup 1.0000x reference)
#include <cuda_runtime.h>

// Problem constants
#define Bn     32
#define Nn     2048
#define PDn    2
#define LATn   128
#define Hn     256
#define STEPSn 5
#define DINn   131
#define NPTS   (Bn * Nn)        // 65536
#define PPC    32               // points per CTA
#define KC     32               // k-chunk for weight tiles
#define NCTA   (NPTS / PPC)     // 2048

// Precomputed device-global scratch (no allocation allowed)
__device__ __align__(16) float g_W2T[Hn * Hn];   // [k][j] = W2[j][k]
__device__ __align__(16) float g_MT [Hn * Hn];   // [k][j] = W2[j][k]*(W1[k,0]W3[0,j]+W1[k,1]W3[1,j])
__device__ __align__(16) float g_base[Bn * Hn];  // b1[k] + sum_l W1[k,3+l] z[b,l]
__device__ __align__(16) float g_c0[Hn], g_c1[Hn], g_ct[Hn], g_csum[Hn];

__device__ __forceinline__ float ftanh(float x) {
    // tanh(x) = 1 - 2/(exp(2x)+1); exact limits at +/-inf, ~1e-6 rel error.
    float e = __expf(2.0f * x);
    return 1.0f - __fdividef(2.0f, e + 1.0f);
}

// ---------------------------------------------------------------------------
// Precompute 1: per-row W1 decomposition + per-batch base vectors
// ---------------------------------------------------------------------------
__global__ void precomp_aux(const float* __restrict__ W1,
                            const float* __restrict__ b1,
                            const float* __restrict__ z) {
    int k = threadIdx.x;            // 256 threads, 1 block
    const float* row = W1 + k * DINn;
    float c0 = row[0], c1 = row[1], ct = row[2];
    float s = 0.f;
#pragma unroll 8
    for (int l = 0; l < LATn; ++l) s += row[3 + l];
    g_c0[k] = c0; g_c1[k] = c1; g_ct[k] = ct; g_csum[k] = s;
    float bk = b1[k];
    for (int b = 0; b < Bn; ++b) {
        float d = bk;
#pragma unroll 8
        for (int l = 0; l < LATn; ++l) d += row[3 + l] * z[b * LATn + l];
        g_base[b * Hn + k] = d;
    }
}

// ---------------------------------------------------------------------------
// Precompute 2: W2 transpose + fused divergence matrix M (transposed)
// ---------------------------------------------------------------------------
__global__ void precomp_mat(const float* __restrict__ W1,
                            const float* __restrict__ W2,
                            const float* __restrict__ W3) {
    int j = blockIdx.x;             // 256 blocks
    int k = threadIdx.x;            // 256 threads
    float w = W2[j * Hn + k];
    g_W2T[k * Hn + j] = w;
    float c0 = W1[k * DINn + 0];
    float c1 = W1[k * DINn + 1];
    g_MT[k * Hn + j] = w * (c0 * W3[j] + c1 * W3[Hn + j]);
}

// ---------------------------------------------------------------------------
// Main fused CNF kernel: each CTA integrates 32 points through all 5 steps.
// ---------------------------------------------------------------------------
__global__ void __launch_bounds__(256, 1)
cnf_kernel(const float* __restrict__ x,
           const float* __restrict__ b2,
           const float* __restrict__ W3,
           const float* __restrict__ b3,
           const float* __restrict__ osc,
           float* __restrict__ out,
           int out_size) {
    extern __shared__ float sm[];
    float* h1s = sm;                 // [256][32]
    float* g1s = sm + 8192;          // [256][32]
    float* wsm = sm + 16384;         // [KC][256]  (also reused as reduction buf, stride 33)
    float* msm = sm + 24576;         // [KC][256]
    float* xs0 = sm + 32768;         // [32]
    float* xs1 = xs0 + 32;           // [32]
    float* ss  = xs1 + 32;           // [32]
    float* red = ss + 32;            // [96]

    const int tid = threadIdx.x;
    const int gp0 = blockIdx.x * PPC;
    const int b   = gp0 >> 11;       // batch (2048 points per batch; PPC | 2048)

    if (tid < PPC) {
        int gp = gp0 + tid;
        xs0[tid] = x[gp * 2 + 0];
        xs1[tid] = x[gp * 2 + 1];
        ss[tid]  = 0.f;
    }
    __syncthreads();

    const float scale = __ldg(osc);
    const float dt = 1.0f / (float)STEPSn;
    const float b30 = __ldg(b3);
    const float b31 = __ldg(b3 + 1);

    const int p_pre = tid & 31;      // pre-activation phase mapping
    const int kg    = tid >> 5;
    const int jt    = tid & 63;      // matvec phase mapping: 4 j's
    const int pt    = tid >> 6;      //                       8 p's

    const float* baseb = g_base + b * Hn;

#pragma unroll 1
    for (int step = 0; step < STEPSn; ++step) {
        float tcur = dt * (float)step;

        // --- layer 1 (elementwise thanks to context collapse) ---
        {
            float sp = ss[p_pre], x0 = xs0[p_pre], x1 = xs1[p_pre];
#pragma unroll 8
            for (int kk2 = 0; kk2 < 32; ++kk2) {
                int k = kg * 32 + kk2;
                float pre = baseb[k] + tcur * g_ct[k] + sp * g_csum[k]
                          + x0 * g_c0[k] + x1 * g_c1[k];
                float h = ftanh(pre);
                h1s[k * PPC + p_pre] = h;
                g1s[k * PPC + p_pre] = 1.f - h * h;
            }
        }
        __syncthreads();

        // --- two fused 256x256 matvecs: a = W2 h1, d = M g1 ---
        float accA[4][8], accD[4][8];
#pragma unroll
        for (int jj = 0; jj < 4; ++jj)
#pragma unroll
            for (int pp = 0; pp < 8; ++pp) { accA[jj][pp] = 0.f; accD[jj][pp] = 0.f; }

        for (int kk = 0; kk < Hn; kk += KC) {
            // stage weight tiles (coalesced float4)
            const float4* gw = reinterpret_cast<const float4*>(g_W2T + kk * Hn);
            const float4* gm = reinterpret_cast<const float4*>(g_MT  + kk * Hn);
            float4* sw = reinterpret_cast<float4*>(wsm);
            float4* smm = reinterpret_cast<float4*>(msm);
#pragma unroll
            for (int i = 0; i < (KC * Hn / 4) / 256; ++i) {  // 8 iters
                int idx = i * 256 + tid;
                sw[idx]  = gw[idx];
                smm[idx] = gm[idx];
            }
            __syncthreads();

#pragma unroll 8
            for (int k = 0; k < KC; ++k) {
                float4 wv = *reinterpret_cast<const float4*>(wsm + k * Hn + (jt << 2));
                float4 mv = *reinterpret_cast<const float4*>(msm + k * Hn + (jt << 2));
                const float* hp = h1s + (kk + k) * PPC + (pt << 3);   // FIXED: global k row
                const float* gq = g1s + (kk + k) * PPC + (pt << 3);   // FIXED: global k row
                float4 h0 = *reinterpret_cast<const float4*>(hp);
                float4 h1v = *reinterpret_cast<const float4*>(hp + 4);
                float4 g0 = *reinterpret_cast<const float4*>(gq);
                float4 g1v = *reinterpret_cast<const float4*>(gq + 4);
                float wa[4] = {wv.x, wv.y, wv.z, wv.w};
                float ma[4] = {mv.x, mv.y, mv.z, mv.w};
                float ha[8] = {h0.x, h0.y, h0.z, h0.w, h1v.x, h1v.y, h1v.z, h1v.w};
                float ga[8] = {g0.x, g0.y, g0.z, g0.w, g1v.x, g1v.y, g1v.z, g1v.w};
#pragma unroll
                for (int jj = 0; jj < 4; ++jj)
#pragma unroll
                    for (int pp = 0; pp < 8; ++pp) {
                        accA[jj][pp] = fmaf(wa[jj], ha[pp], accA[jj][pp]);
                        accD[jj][pp] = fmaf(ma[jj], ga[pp], accD[jj][pp]);
                    }
            }
            __syncthreads();  // before tile overwrite / partial-buffer reuse
        }

        // --- epilogue: h2, g2, per-thread partials for v0, v1, div ---
        float pv0[8], pv1[8], pdv[8];
#pragma unroll
        for (int pp = 0; pp < 8; ++pp) { pv0[pp] = 0.f; pv1[pp] = 0.f; pdv[pp] = 0.f; }
#pragma unroll
        for (int jj = 0; jj < 4; ++jj) {
            int j = (jt << 2) + jj;
            float b2j = __ldg(b2 + j);
            float w30 = __ldg(W3 + j);
            float w31 = __ldg(W3 + Hn + j);
#pragma unroll
            for (int pp = 0; pp < 8; ++pp) {
                float h2 = ftanh(accA[jj][pp] + b2j);
                float g2 = 1.f - h2 * h2;
                pv0[pp] += w30 * h2;
                pv1[pp] += w31 * h2;
                pdv[pp] += g2 * accD[jj][pp];
            }
        }
        // partials -> smem (stride-33 padding for conflict-free access)
#pragma unroll
        for (int pp = 0; pp < 8; ++pp) {
            int p = (pt << 3) + pp;
            wsm[jt * 33 + p]            = pv0[pp];
            wsm[2112 + jt * 33 + p]     = pv1[pp];
            wsm[4224 + jt * 33 + p]     = pdv[pp];
        }
        __syncthreads();
        if (tid < 96) {
            int kind = tid >> 5, p = tid & 31;
            const float* src = wsm + kind * 2112 + p;
            float s = 0.f;
#pragma unroll
            for (int j2 = 0; j2 < 64; ++j2) s += src[j2 * 33];
            red[kind * 32 + p] = s;
        }
        __syncthreads();
        if (tid < PPC) {
            float v0 = (red[tid]      + b30) * scale;
            float v1 = (red[32 + tid] + b31) * scale;
            float dv =  red[64 + tid] * scale;
            xs0[tid] += v0 * dt;
            xs1[tid] += v1 * dt;
            ss[tid]  += dv * dt;
        }
        __syncthreads();
    }

    if (tid < PPC) {
        int gp = gp0 + tid;
        out[gp * 2 + 0] = xs0[tid];
        out[gp * 2 + 1] = xs1[tid];
        if (out_size >= NPTS * PDn + NPTS)
            out[NPTS * PDn + gp] = ss[tid];
    }
}

// ---------------------------------------------------------------------------
// kernel_launch
// Inputs (metadata order): x, z, W1, b1, W2, b2, W3, b3, out_scale
// Output: concat(y.flatten(), log_det.flatten()) as float32
// ---------------------------------------------------------------------------
extern "C" void kernel_launch(void* const* d_in, const int* in_sizes, int n_in,
                              void* d_out, int out_size) {
    const float* x   = (const float*)d_in[0];
    const float* z   = (const float*)d_in[1];
    const float* W1  = (const float*)d_in[2];
    const float* b1  = (const float*)d_in[3];
    const float* W2  = (const float*)d_in[4];
    const float* b2  = (const float*)d_in[5];
    const float* W3  = (const float*)d_in[6];
    const float* b3  = (const float*)d_in[7];
    const float* osc = (const float*)d_in[8];
    float* out = (float*)d_out;

    precomp_aux<<<1, 256>>>(W1, b1, z);
    precomp_mat<<<256, 256>>>(W1, W2, W3);

    const int smem_bytes = (32768 + 192) * (int)sizeof(float);  // 131840 B
    cudaFuncSetAttribute(cnf_kernel, cudaFuncAttributeMaxDynamicSharedMemorySize,
                         smem_bytes);

    cnf_kernel<<<NCTA, 256, smem_bytes>>>(x, b2, W3, b3, osc, out, out_size);
}

// round 3
// speedup vs baseline: 1.1982x; 1.1982x over previous
#include <cuda_runtime.h>
#include <cstdint>

// Problem constants
#define Bn     32
#define Nn     2048
#define PDn    2
#define LATn   128
#define Hn     256
#define STEPSn 5
#define DINn   131
#define NPTS   (Bn * Nn)        // 65536
#define PPC    32               // points per CTA
#define KC     32               // k-chunk for weight tiles
#define NCTA   (NPTS / PPC)     // 2048

// Precomputed device-global scratch (no allocation allowed)
__device__ __align__(16) float g_W2T[Hn * Hn];   // [k][j] = W2[j][k]
__device__ __align__(16) float g_MT [Hn * Hn];   // [k][j] = W2[j][k]*(W1[k,0]W3[0,j]+W1[k,1]W3[1,j])
__device__ __align__(16) float g_base[Bn * Hn];  // b1[k] + sum_l W1[k,3+l] z[b,l]
__device__ __align__(16) float g_c0[Hn], g_c1[Hn], g_ct[Hn], g_csum[Hn];

__device__ __forceinline__ float ftanh(float x) {
    float e = __expf(2.0f * x);
    return 1.0f - __fdividef(2.0f, e + 1.0f);
}

// --- packed fp32x2 helpers (sm_103a FFMA2 path; ptxas never auto-fuses) ---
__device__ __forceinline__ unsigned long long pack2(float v) {
    unsigned long long r;
    unsigned u = __float_as_uint(v);
    asm("mov.b64 %0, {%1, %1};" : "=l"(r) : "r"(u));
    return r;
}
__device__ __forceinline__ void fma2(unsigned long long& acc,
                                     unsigned long long a,
                                     unsigned long long b) {
    asm("fma.rn.f32x2 %0, %1, %2, %0;" : "+l"(acc) : "l"(a), "l"(b));
}
__device__ __forceinline__ void unpack2(float& lo, float& hi, unsigned long long v) {
    unsigned a, b;
    asm("mov.b64 {%0, %1}, %2;" : "=r"(a), "=r"(b) : "l"(v));
    lo = __uint_as_float(a);
    hi = __uint_as_float(b);
}

// ---------------------------------------------------------------------------
// Precompute 1: per-row W1 decomposition + per-batch base vectors
// Parallelized over batches: grid=32 (one block per batch).
// ---------------------------------------------------------------------------
__global__ void precomp_aux(const float* __restrict__ W1,
                            const float* __restrict__ b1,
                            const float* __restrict__ z) {
    int k = threadIdx.x;            // 256 threads
    int b = blockIdx.x;             // 32 blocks
    const float* row = W1 + k * DINn;
    float d = b1[k];
    const float* zb = z + b * LATn;
#pragma unroll 8
    for (int l = 0; l < LATn; ++l) d += row[3 + l] * zb[l];
    g_base[b * Hn + k] = d;
    if (b == 0) {
        float s = 0.f;
#pragma unroll 8
        for (int l = 0; l < LATn; ++l) s += row[3 + l];
        g_c0[k] = row[0]; g_c1[k] = row[1]; g_ct[k] = row[2]; g_csum[k] = s;
    }
}

// ---------------------------------------------------------------------------
// Precompute 2: W2 transpose + fused divergence matrix M (transposed)
// ---------------------------------------------------------------------------
__global__ void precomp_mat(const float* __restrict__ W1,
                            const float* __restrict__ W2,
                            const float* __restrict__ W3) {
    int j = blockIdx.x;             // 256 blocks
    int k = threadIdx.x;            // 256 threads
    float w = W2[j * Hn + k];
    g_W2T[k * Hn + j] = w;
    float c0 = W1[k * DINn + 0];
    float c1 = W1[k * DINn + 1];
    g_MT[k * Hn + j] = w * (c0 * W3[j] + c1 * W3[Hn + j]);
}

// ---------------------------------------------------------------------------
// Main fused CNF kernel: each CTA integrates 32 points through all 5 steps.
// Inner product engine uses packed fma.rn.f32x2 (2 fp32 FMA / instr).
// ---------------------------------------------------------------------------
__global__ void __launch_bounds__(256, 1)
cnf_kernel(const float* __restrict__ x,
           const float* __restrict__ b2,
           const float* __restrict__ W3,
           const float* __restrict__ b3,
           const float* __restrict__ osc,
           float* __restrict__ out,
           int out_size) {
    extern __shared__ float sm[];
    float* h1s = sm;                 // [256][32]
    float* g1s = sm + 8192;         // [256][32]
    float* wsm = sm + 16384;        // [KC][256] (reused as reduction buf)
    float* msm = sm + 24576;        // [KC][256]
    float* xs0 = sm + 32768;        // [32]
    float* xs1 = xs0 + 32;          // [32]
    float* ss  = xs1 + 32;          // [32]
    float* red = ss + 32;           // [96]

    const int tid = threadIdx.x;
    const int gp0 = blockIdx.x * PPC;
    const int b   = gp0 >> 11;      // batch (2048 points per batch)

    if (tid < PPC) {
        int gp = gp0 + tid;
        xs0[tid] = x[gp * 2 + 0];
        xs1[tid] = x[gp * 2 + 1];
        ss[tid]  = 0.f;
    }
    __syncthreads();

    const float scale = __ldg(osc);
    const float dt = 1.0f / (float)STEPSn;
    const float b30 = __ldg(b3);
    const float b31 = __ldg(b3 + 1);

    const int p_pre = tid & 31;     // layer-1 phase mapping
    const int kg    = tid >> 5;
    const int jt    = tid & 63;     // matvec phase: 4 j's per thread
    const int pt    = tid >> 6;     //               8 p's per thread (4 pairs)

    const float* baseb = g_base + b * Hn;

#pragma unroll 1
    for (int step = 0; step < STEPSn; ++step) {
        float tcur = dt * (float)step;

        // --- layer 1 (elementwise via context collapse) ---
        {
            float sp = ss[p_pre], x0 = xs0[p_pre], x1 = xs1[p_pre];
#pragma unroll 8
            for (int kk2 = 0; kk2 < 32; ++kk2) {
                int k = kg * 32 + kk2;
                float pre = baseb[k] + tcur * g_ct[k] + sp * g_csum[k]
                          + x0 * g_c0[k] + x1 * g_c1[k];
                float h = ftanh(pre);
                h1s[k * PPC + p_pre] = h;
                g1s[k * PPC + p_pre] = 1.f - h * h;
            }
        }
        __syncthreads();

        // --- two fused 256x256 matvecs: a = W2 h1, d = M g1 (packed f32x2) ---
        unsigned long long accA[4][4], accD[4][4];
#pragma unroll
        for (int jj = 0; jj < 4; ++jj)
#pragma unroll
            for (int q = 0; q < 4; ++q) { accA[jj][q] = 0ull; accD[jj][q] = 0ull; }

        for (int kk = 0; kk < Hn; kk += KC) {
            // stage weight tiles (coalesced float4)
            const float4* gw = reinterpret_cast<const float4*>(g_W2T + kk * Hn);
            const float4* gm = reinterpret_cast<const float4*>(g_MT  + kk * Hn);
            float4* sw = reinterpret_cast<float4*>(wsm);
            float4* smm = reinterpret_cast<float4*>(msm);
#pragma unroll
            for (int i = 0; i < (KC * Hn / 4) / 256; ++i) {  // 8 iters
                int idx = i * 256 + tid;
                sw[idx]  = gw[idx];
                smm[idx] = gm[idx];
            }
            __syncthreads();

#pragma unroll 8
            for (int k = 0; k < KC; ++k) {
                float4 wv = *reinterpret_cast<const float4*>(wsm + k * Hn + (jt << 2));
                float4 mv = *reinterpret_cast<const float4*>(msm + k * Hn + (jt << 2));
                const float* hp = h1s + (kk + k) * PPC + (pt << 3);
                const float* gq = g1s + (kk + k) * PPC + (pt << 3);
                // packed pairs over consecutive points (broadcast within warp)
                ulonglong2 hA = *reinterpret_cast<const ulonglong2*>(hp);     // (p0,p1),(p2,p3)
                ulonglong2 hB = *reinterpret_cast<const ulonglong2*>(hp + 4); // (p4,p5),(p6,p7)
                ulonglong2 gA = *reinterpret_cast<const ulonglong2*>(gq);
                ulonglong2 gB = *reinterpret_cast<const ulonglong2*>(gq + 4);
                unsigned long long hh[4] = {hA.x, hA.y, hB.x, hB.y};
                unsigned long long gg[4] = {gA.x, gA.y, gB.x, gB.y};
                float wa[4] = {wv.x, wv.y, wv.z, wv.w};
                float ma[4] = {mv.x, mv.y, mv.z, mv.w};
#pragma unroll
                for (int jj = 0; jj < 4; ++jj) {
                    unsigned long long wp = pack2(wa[jj]);
                    unsigned long long mp = pack2(ma[jj]);
#pragma unroll
                    for (int q = 0; q < 4; ++q) {
                        fma2(accA[jj][q], wp, hh[q]);
                        fma2(accD[jj][q], mp, gg[q]);
                    }
                }
            }
            __syncthreads();  // before tile overwrite / buffer reuse
        }

        // --- epilogue: h2, g2, per-thread partials for v0, v1, div ---
        float pv0[8], pv1[8], pdv[8];
#pragma unroll
        for (int pp = 0; pp < 8; ++pp) { pv0[pp] = 0.f; pv1[pp] = 0.f; pdv[pp] = 0.f; }
#pragma unroll
        for (int jj = 0; jj < 4; ++jj) {
            int j = (jt << 2) + jj;
            float b2j = __ldg(b2 + j);
            float w30 = __ldg(W3 + j);
            float w31 = __ldg(W3 + Hn + j);
#pragma unroll
            for (int q = 0; q < 4; ++q) {
                float a0, a1, d0, d1;
                unpack2(a0, a1, accA[jj][q]);
                unpack2(d0, d1, accD[jj][q]);
                float h2a = ftanh(a0 + b2j);
                float h2b = ftanh(a1 + b2j);
                float g2a = 1.f - h2a * h2a;
                float g2b = 1.f - h2b * h2b;
                pv0[2*q]   += w30 * h2a;  pv0[2*q+1] += w30 * h2b;
                pv1[2*q]   += w31 * h2a;  pv1[2*q+1] += w31 * h2b;
                pdv[2*q]   += g2a * d0;   pdv[2*q+1] += g2b * d1;
            }
        }
        // partials -> smem (stride-33 padding, conflict-free)
#pragma unroll
        for (int pp = 0; pp < 8; ++pp) {
            int p = (pt << 3) + pp;
            wsm[jt * 33 + p]        = pv0[pp];
            wsm[2112 + jt * 33 + p] = pv1[pp];
            wsm[4224 + jt * 33 + p] = pdv[pp];
        }
        __syncthreads();
        if (tid < 96) {
            int kind = tid >> 5, p = tid & 31;
            const float* src = wsm + kind * 2112 + p;
            float s = 0.f;
#pragma unroll
            for (int j2 = 0; j2 < 64; ++j2) s += src[j2 * 33];
            red[kind * 32 + p] = s;
        }
        __syncthreads();
        if (tid < PPC) {
            float v0 = (red[tid]      + b30) * scale;
            float v1 = (red[32 + tid] + b31) * scale;
            float dv =  red[64 + tid] * scale;
            xs0[tid] += v0 * dt;
            xs1[tid] += v1 * dt;
            ss[tid]  += dv * dt;
        }
        __syncthreads();
    }

    if (tid < PPC) {
        int gp = gp0 + tid;
        out[gp * 2 + 0] = xs0[tid];
        out[gp * 2 + 1] = xs1[tid];
        if (out_size >= NPTS * PDn + NPTS)
            out[NPTS * PDn + gp] = ss[tid];
    }
}

// ---------------------------------------------------------------------------
// kernel_launch
// Inputs (metadata order): x, z, W1, b1, W2, b2, W3, b3, out_scale
// ---------------------------------------------------------------------------
extern "C" void kernel_launch(void* const* d_in, const int* in_sizes, int n_in,
                              void* d_out, int out_size) {
    const float* x   = (const float*)d_in[0];
    const float* z   = (const float*)d_in[1];
    const float* W1  = (const float*)d_in[2];
    const float* b1  = (const float*)d_in[3];
    const float* W2  = (const float*)d_in[4];
    const float* b2  = (const float*)d_in[5];
    const float* W3  = (const float*)d_in[6];
    const float* b3  = (const float*)d_in[7];
    const float* osc = (const float*)d_in[8];
    float* out = (float*)d_out;

    precomp_aux<<<Bn, 256>>>(W1, b1, z);
    precomp_mat<<<256, 256>>>(W1, W2, W3);

    const int smem_bytes = (32768 + 192) * (int)sizeof(float);  // 131840 B
    cudaFuncSetAttribute(cnf_kernel, cudaFuncAttributeMaxDynamicSharedMemorySize,
                         smem_bytes);

    cnf_kernel<<<NCTA, 256, smem_bytes>>>(x, b2, W3, b3, osc, out, out_size);
}

// round 5
// speedup vs baseline: 3.1649x; 2.6413x over previous
#include <cuda_runtime.h>
#include <cuda_fp16.h>
#include <cstdint>

// ---------------------------------------------------------------------------
// Problem constants
// ---------------------------------------------------------------------------
#define Bn     32
#define Nn     2048
#define PDn    2
#define LATn   128
#define Hn     256
#define STEPSn 5
#define DINn   131
#define NPTS   (Bn * Nn)         // 65536
#define PPC    128               // points per CTA (= GEMM M)
#define NCTA   (NPTS / PPC)      // 512
#define KCH    64                // K-chunk
#define NCHUNK (Hn / KCH)        // 4
#define NTHREADS 256

// ---------------------------------------------------------------------------
// Device globals
// ---------------------------------------------------------------------------
// fp16 weights, chunk-major: [matrix(2: W2, M)][chunk(4)][j=256][kk=64]
__device__ __align__(16) __half g_W16[2 * NCHUNK * Hn * KCH];
__device__ __align__(16) float g_base[Bn * Hn];
__device__ __align__(16) float g_c0[Hn], g_c1[Hn], g_ct[Hn], g_csum[Hn];

__device__ __forceinline__ float ftanh(float x) {
    float e = __expf(2.0f * x);
    return 1.0f - __fdividef(2.0f, e + 1.0f);
}
__device__ __forceinline__ uint32_t smem_u32(const void* p) {
    uint32_t a;
    asm("{ .reg .u64 t; cvta.to.shared.u64 t, %1; cvt.u32.u64 %0, t; }"
        : "=r"(a) : "l"(p));
    return a;
}
__device__ __forceinline__ void ldsm4(uint32_t& r0, uint32_t& r1,
                                      uint32_t& r2, uint32_t& r3, uint32_t addr) {
    asm volatile("ldmatrix.sync.aligned.m8n8.x4.shared.b16 {%0,%1,%2,%3}, [%4];"
                 : "=r"(r0), "=r"(r1), "=r"(r2), "=r"(r3) : "r"(addr));
}
__device__ __forceinline__ void mma16816(float* d, const uint32_t* a,
                                         uint32_t b0, uint32_t b1) {
    asm volatile(
        "mma.sync.aligned.m16n8k16.row.col.f32.f16.f16.f32 "
        "{%0,%1,%2,%3},{%4,%5,%6,%7},{%8,%9},{%0,%1,%2,%3};"
        : "+f"(d[0]), "+f"(d[1]), "+f"(d[2]), "+f"(d[3])
        : "r"(a[0]), "r"(a[1]), "r"(a[2]), "r"(a[3]), "r"(b0), "r"(b1));
}

// ---------------------------------------------------------------------------
// Precompute 1: per-row W1 decomposition + per-batch base vectors
// ---------------------------------------------------------------------------
__global__ void precomp_aux(const float* __restrict__ W1,
                            const float* __restrict__ b1,
                            const float* __restrict__ z) {
    int k = threadIdx.x;
    int b = blockIdx.x;
    const float* row = W1 + k * DINn;
    float d = b1[k];
    const float* zb = z + b * LATn;
#pragma unroll 8
    for (int l = 0; l < LATn; ++l) d += row[3 + l] * zb[l];
    g_base[b * Hn + k] = d;
    if (b == 0) {
        float s = 0.f;
#pragma unroll 8
        for (int l = 0; l < LATn; ++l) s += row[3 + l];
        g_c0[k] = row[0]; g_c1[k] = row[1]; g_ct[k] = row[2]; g_csum[k] = s;
    }
}

// ---------------------------------------------------------------------------
// Precompute 2: W2 and fused divergence matrix M -> fp16, chunk-major
// ---------------------------------------------------------------------------
__global__ void precomp_w(const float* __restrict__ W1,
                          const float* __restrict__ W2,
                          const float* __restrict__ W3) {
    int j = blockIdx.x;   // 256
    int k = threadIdx.x;  // 256
    float w2 = W2[j * Hn + k];
    float mm = w2 * (W1[k * DINn] * W3[j] + W1[k * DINn + 1] * W3[Hn + j]);
    int chunk = k >> 6, kk = k & 63;
    int idx = chunk * (Hn * KCH) + j * KCH + kk;
    g_W16[idx] = __float2half_rn(w2);
    g_W16[NCHUNK * Hn * KCH + idx] = __float2half_rn(mm);
}

// ---------------------------------------------------------------------------
// SMEM layout (byte offsets)
// ---------------------------------------------------------------------------
#define SM_C0    0
#define SM_C1    1024
#define SM_CT    2048
#define SM_CS    3072
#define SM_BASE  4096
#define SM_B2    5120
#define SM_W30   6144
#define SM_W31   7168
#define SM_X0    8192
#define SM_X1    8704
#define SM_SS    9216
#define SM_PART  9728          // [3][4][128] f32 = 6144
#define SM_AHI   16384         // 128 x 72 halfs = 18432
#define SM_ALO   34816         // 18432
#define SM_B     53248         // 256 x 72 halfs = 36864
#define SM_G2    90112         // 128 x 264 halfs = 67584
#define SM_TOTAL 157696

// ---------------------------------------------------------------------------
// Main fused CNF kernel (mma.sync tensor cores, fp16 hi/lo split A-side)
// ---------------------------------------------------------------------------
__global__ void __launch_bounds__(NTHREADS, 1)
cnf_kernel(const float* __restrict__ x,
           const float* __restrict__ b2,
           const float* __restrict__ W3,
           const float* __restrict__ b3,
           const float* __restrict__ osc,
           float* __restrict__ out,
           int out_size) {
    extern __shared__ char smem[];
    float* sf = reinterpret_cast<float*>(smem);
    const uint32_t sb = smem_u32(smem);

    const int tid  = threadIdx.x;
    const int wid  = tid >> 5;
    const int lane = tid & 31;
    const int gp0  = blockIdx.x * PPC;
    const int bidx = gp0 >> 11;

    // load constants into smem
    sf[(SM_C0 >> 2) + tid]   = g_c0[tid];
    sf[(SM_C1 >> 2) + tid]   = g_c1[tid];
    sf[(SM_CT >> 2) + tid]   = g_ct[tid];
    sf[(SM_CS >> 2) + tid]   = g_csum[tid];
    sf[(SM_BASE >> 2) + tid] = g_base[bidx * Hn + tid];
    sf[(SM_B2 >> 2) + tid]   = b2[tid];
    sf[(SM_W30 >> 2) + tid]  = W3[tid];
    sf[(SM_W31 >> 2) + tid]  = W3[Hn + tid];
    if (tid < PPC) {
        int gp = gp0 + tid;
        sf[(SM_X0 >> 2) + tid] = x[gp * 2 + 0];
        sf[(SM_X1 >> 2) + tid] = x[gp * 2 + 1];
        sf[(SM_SS >> 2) + tid] = 0.f;
    }
    __syncthreads();

    const float scale = __ldg(osc);
    const float dt  = 1.0f / (float)STEPSn;
    const float b30 = __ldg(b3), b31 = __ldg(b3 + 1);

    // layer-1 mapping
    const int p_mine = tid >> 1;
    const int khalf  = tid & 1;
    // mma warp tiling: 2 (M) x 4 (N)
    const int warp_m = wid >> 2;
    const int warp_n = wid & 3;
    const int m0w = warp_m * 64;
    const int n0w = warp_n * 64;
    const int grp = lane >> 2, tig = lane & 3;
    // lane-invariant ldmatrix offsets
    const uint32_t aoff = (uint32_t)(lane & 15) * 144u + ((uint32_t)(lane >> 4) << 4);
    const uint32_t boff = ((uint32_t)((lane & 7) + ((lane >> 4) << 3))) * 144u
                        + (((uint32_t)(lane >> 3) & 1u) << 4);

    const float* c0s = sf + (SM_C0 >> 2);
    const float* c1s = sf + (SM_C1 >> 2);
    const float* cts = sf + (SM_CT >> 2);
    const float* css = sf + (SM_CS >> 2);
    const float* bas = sf + (SM_BASE >> 2);
    const float* b2s = sf + (SM_B2 >> 2);
    const float* w30s = sf + (SM_W30 >> 2);
    const float* w31s = sf + (SM_W31 >> 2);
    float* part = sf + (SM_PART >> 2);

#pragma unroll 1
    for (int step = 0; step < STEPSn; ++step) {
        const float tcur = dt * (float)step;
        const float px0 = sf[(SM_X0 >> 2) + p_mine];
        const float px1 = sf[(SM_X1 >> 2) + p_mine];
        const float psv = sf[(SM_SS >> 2) + p_mine];

#pragma unroll 1
        for (int pass = 0; pass < 2; ++pass) {
            float acc[4][8][4];
#pragma unroll
            for (int mi = 0; mi < 4; ++mi)
#pragma unroll
                for (int ni = 0; ni < 8; ++ni)
#pragma unroll
                    for (int q = 0; q < 4; ++q) acc[mi][ni][q] = 0.f;

#pragma unroll 1
            for (int chunk = 0; chunk < NCHUNK; ++chunk) {
                // ---- layer-1 activations for this chunk (h or g), fp16 split ----
                {
                    const int kkb = khalf * 32;
#pragma unroll
                    for (int kk2 = 0; kk2 < 32; kk2 += 2) {
                        int kk = kkb + kk2;
                        int k = chunk * KCH + kk;
                        float u0 = bas[k] + tcur * cts[k] + psv * css[k]
                                 + px0 * c0s[k] + px1 * c1s[k];
                        float u1 = bas[k+1] + tcur * cts[k+1] + psv * css[k+1]
                                 + px0 * c0s[k+1] + px1 * c1s[k+1];
                        float h0 = ftanh(u0), h1 = ftanh(u1);
                        if (pass) { h0 = 1.f - h0 * h0; h1 = 1.f - h1 * h1; }
                        __half H0 = __float2half_rn(h0);
                        __half H1 = __float2half_rn(h1);
                        __half L0 = __float2half_rn(h0 - __half2float(H0));
                        __half L1 = __float2half_rn(h1 - __half2float(H1));
                        uint32_t o = (uint32_t)p_mine * 144u + (uint32_t)kk * 2u;
                        *reinterpret_cast<__half2*>(smem + SM_AHI + o) = __halves2half2(H0, H1);
                        *reinterpret_cast<__half2*>(smem + SM_ALO + o) = __halves2half2(L0, L1);
                    }
                }
                // ---- copy B chunk (fp16, 32 KB) ----
                {
                    const uint4* src = reinterpret_cast<const uint4*>(
                        g_W16 + (pass * NCHUNK + chunk) * (Hn * KCH));
#pragma unroll
                    for (int i = 0; i < 8; ++i) {
                        int idx = i * 256 + tid;
                        int j = idx >> 3, kb = idx & 7;
                        *reinterpret_cast<uint4*>(smem + SM_B + j * 144 + kb * 16) = src[idx];
                    }
                }
                __syncthreads();

                // ---- MMA: 2 terms (hi, lo) x 4 ksteps ----
#pragma unroll
                for (int term = 0; term < 2; ++term) {
                    const uint32_t abase = sb + (term ? SM_ALO : SM_AHI);
#pragma unroll
                    for (int ks = 0; ks < 4; ++ks) {
                        uint32_t a[4][4];
#pragma unroll
                        for (int mi = 0; mi < 4; ++mi) {
                            uint32_t ad = abase + (uint32_t)(m0w + mi * 16) * 144u
                                        + (uint32_t)ks * 32u + aoff;
                            ldsm4(a[mi][0], a[mi][1], a[mi][2], a[mi][3], ad);
                        }
#pragma unroll
                        for (int ng = 0; ng < 4; ++ng) {
                            uint32_t r0, r1, r2, r3;
                            uint32_t bd = sb + SM_B + (uint32_t)(n0w + ng * 16) * 144u
                                        + (uint32_t)ks * 32u + boff;
                            ldsm4(r0, r1, r2, r3, bd);
#pragma unroll
                            for (int mi = 0; mi < 4; ++mi) {
                                mma16816(acc[mi][ng * 2],     a[mi], r0, r1);
                                mma16816(acc[mi][ng * 2 + 1], a[mi], r2, r3);
                            }
                        }
                    }
                }
                __syncthreads();
            }

            // ---- epilogue ----
            if (pass == 0) {
                float v0p[8], v1p[8];
#pragma unroll
                for (int i = 0; i < 8; ++i) { v0p[i] = 0.f; v1p[i] = 0.f; }
#pragma unroll
                for (int mi = 0; mi < 4; ++mi) {
                    int p0 = m0w + mi * 16 + grp;
#pragma unroll
                    for (int ni = 0; ni < 8; ++ni) {
                        int j0 = n0w + ni * 8 + tig * 2;
                        float* c = acc[mi][ni];
                        float h00 = ftanh(c[0] + b2s[j0]);
                        float h01 = ftanh(c[1] + b2s[j0 + 1]);
                        float h10 = ftanh(c[2] + b2s[j0]);
                        float h11 = ftanh(c[3] + b2s[j0 + 1]);
                        v0p[2*mi]   += w30s[j0] * h00 + w30s[j0+1] * h01;
                        v0p[2*mi+1] += w30s[j0] * h10 + w30s[j0+1] * h11;
                        v1p[2*mi]   += w31s[j0] * h00 + w31s[j0+1] * h01;
                        v1p[2*mi+1] += w31s[j0] * h10 + w31s[j0+1] * h11;
                        uint32_t o0 = (uint32_t)p0 * 528u + (uint32_t)j0 * 2u;
                        *reinterpret_cast<__half2*>(smem + SM_G2 + o0) =
                            __floats2half2_rn(1.f - h00 * h00, 1.f - h01 * h01);
                        *reinterpret_cast<__half2*>(smem + SM_G2 + o0 + 8 * 528u) =
                            __floats2half2_rn(1.f - h10 * h10, 1.f - h11 * h11);
                    }
                }
#pragma unroll
                for (int i = 0; i < 8; ++i) {
                    v0p[i] += __shfl_xor_sync(0xffffffffu, v0p[i], 1);
                    v0p[i] += __shfl_xor_sync(0xffffffffu, v0p[i], 2);
                    v1p[i] += __shfl_xor_sync(0xffffffffu, v1p[i], 1);
                    v1p[i] += __shfl_xor_sync(0xffffffffu, v1p[i], 2);
                }
                if (tig == 0) {
#pragma unroll
                    for (int i = 0; i < 8; ++i) {
                        int p = m0w + (i >> 1) * 16 + grp + (i & 1) * 8;
                        part[0 * 512 + warp_n * 128 + p] = v0p[i];
                        part[1 * 512 + warp_n * 128 + p] = v1p[i];
                    }
                }
            } else {
                float dvp[8];
#pragma unroll
                for (int i = 0; i < 8; ++i) dvp[i] = 0.f;
#pragma unroll
                for (int mi = 0; mi < 4; ++mi) {
                    int p0 = m0w + mi * 16 + grp;
#pragma unroll
                    for (int ni = 0; ni < 8; ++ni) {
                        int j0 = n0w + ni * 8 + tig * 2;
                        float* c = acc[mi][ni];
                        uint32_t o0 = (uint32_t)p0 * 528u + (uint32_t)j0 * 2u;
                        float2 ga = __half22float2(
                            *reinterpret_cast<__half2*>(smem + SM_G2 + o0));
                        float2 gb = __half22float2(
                            *reinterpret_cast<__half2*>(smem + SM_G2 + o0 + 8 * 528u));
                        dvp[2*mi]   += ga.x * c[0] + ga.y * c[1];
                        dvp[2*mi+1] += gb.x * c[2] + gb.y * c[3];
                    }
                }
#pragma unroll
                for (int i = 0; i < 8; ++i) {
                    dvp[i] += __shfl_xor_sync(0xffffffffu, dvp[i], 1);
                    dvp[i] += __shfl_xor_sync(0xffffffffu, dvp[i], 2);
                }
                if (tig == 0) {
#pragma unroll
                    for (int i = 0; i < 8; ++i) {
                        int p = m0w + (i >> 1) * 16 + grp + (i & 1) * 8;
                        part[2 * 512 + warp_n * 128 + p] = dvp[i];
                    }
                }
            }
        }
        __syncthreads();

        // ---- state update ----
        if (tid < PPC) {
            float v0 = b30, v1 = b31, dv = 0.f;
#pragma unroll
            for (int wn = 0; wn < 4; ++wn) {
                v0 += part[0 * 512 + wn * 128 + tid];
                v1 += part[1 * 512 + wn * 128 + tid];
                dv += part[2 * 512 + wn * 128 + tid];
            }
            sf[(SM_X0 >> 2) + tid] += v0 * scale * dt;
            sf[(SM_X1 >> 2) + tid] += v1 * scale * dt;
            sf[(SM_SS >> 2) + tid] += dv * scale * dt;
        }
        __syncthreads();
    }

    if (tid < PPC) {
        int gp = gp0 + tid;
        out[gp * 2 + 0] = sf[(SM_X0 >> 2) + tid];
        out[gp * 2 + 1] = sf[(SM_X1 >> 2) + tid];
        if (out_size >= NPTS * PDn + NPTS)
            out[NPTS * PDn + gp] = sf[(SM_SS >> 2) + tid];
    }
}

// ---------------------------------------------------------------------------
// kernel_launch
// Inputs (metadata order): x, z, W1, b1, W2, b2, W3, b3, out_scale
// ---------------------------------------------------------------------------
extern "C" void kernel_launch(void* const* d_in, const int* in_sizes, int n_in,
                              void* d_out, int out_size) {
    const float* x   = (const float*)d_in[0];
    const float* z   = (const float*)d_in[1];
    const float* W1  = (const float*)d_in[2];
    const float* b1  = (const float*)d_in[3];
    const float* W2  = (const float*)d_in[4];
    const float* b2  = (const float*)d_in[5];
    const float* W3  = (const float*)d_in[6];
    const float* b3  = (const float*)d_in[7];
    const float* osc = (const float*)d_in[8];
    float* out = (float*)d_out;

    precomp_aux<<<Bn, 256>>>(W1, b1, z);
    precomp_w<<<256, 256>>>(W1, W2, W3);

    cudaFuncSetAttribute(cnf_kernel, cudaFuncAttributeMaxDynamicSharedMemorySize,
                         SM_TOTAL);
    cnf_kernel<<<NCTA, NTHREADS, SM_TOTAL>>>(x, b2, W3, b3, osc, out, out_size);
}